// round 14
// baseline (speedup 1.0000x reference)
#include <cuda_runtime.h>
#include <cuda_bf16.h>
#include <mma.h>
#include <cstdint>

using namespace nvcuda;

#define HDIM  512
#define KNBR  32
#define NHEADS 8
#define NBINS 10
#define NMAX  10000
#define MPAD  10112      // ceil(10000/128)*128
#define NEG_SLOPE 0.2f
#define PROJW 1536       // [S | Pn | Wt]

__device__ float g_proj[(size_t)MPAD * PROJW];          // per-node projections (fp32)
__device__ __nv_bfloat16 g_Ahi[(size_t)MPAD * HDIM];
__device__ __nv_bfloat16 g_Alo[(size_t)MPAD * HDIM];
__device__ __nv_bfloat16 g_Bhi[(size_t)PROJW * HDIM];
__device__ __nv_bfloat16 g_Blo[(size_t)PROJW * HDIM];

__device__ __forceinline__ float lrelu(float x) {
    return x >= 0.0f ? x : NEG_SLOPE * x;
}

// ===========================================================================
// Conversions: fp32 -> (hi, lo) bf16 split
// ===========================================================================
__global__ void conv_a_kernel(const float* __restrict__ z, int M, int Mp) {
    int i = blockIdx.x * blockDim.x + threadIdx.x;
    if (i >= Mp * HDIM) return;
    int row = i >> 9;
    float x = (row < M) ? z[i] : 0.0f;
    __nv_bfloat16 h = __float2bfloat16(x);
    g_Ahi[i] = h;
    g_Alo[i] = __float2bfloat16(x - __bfloat162float(h));
}

__global__ void conv_b_kernel(const float* __restrict__ P_w, const float* __restrict__ W_w) {
    int i = blockIdx.x * blockDim.x + threadIdx.x;
    if (i >= PROJW * HDIM) return;
    int j = i >> 9;
    int hcol = i & (HDIM - 1);
    float x;
    if (j < 512)        x = P_w[(size_t)j * 1024 + hcol];
    else if (j < 1024)  x = P_w[(size_t)(j - 512) * 1024 + 512 + hcol];
    else                x = W_w[(size_t)(j - 1024) * 512 + hcol];
    __nv_bfloat16 h = __float2bfloat16(x);
    g_Bhi[i] = h;
    g_Blo[i] = __float2bfloat16(x - __bfloat162float(h));
}

// ===========================================================================
// wmma bf16 3-term GEMM with cp.async DOUBLE BUFFERING.
// CTA tile 128x128, 8 warps (4m x 2n), warp tile 32x64.
// K chunked by 32; 2 buffers x 4 tiles x 128x48 bf16 = 96 KB dynamic smem.
// ===========================================================================
#define KC 32
#define LPAD 48
#define TILE_ELEMS (128 * LPAD)
#define BUF_ELEMS  (4 * TILE_ELEMS)
#define GEMM_SMEM  (2 * BUF_ELEMS * 2)   // 98304 bytes
#define NCHUNK (HDIM / KC)               // 16

__global__ __launch_bounds__(256) void gemm_wmma_kernel(int M) {
    extern __shared__ __nv_bfloat16 sm[];
    const uint32_t smbase = (uint32_t)__cvta_generic_to_shared(sm);

    const int tid = threadIdx.x;
    const int wid = tid >> 5;
    const int bm = blockIdx.y * 128;
    const int bn = blockIdx.x * 128;
    const int wm = wid & 3;
    const int wn = wid >> 2;

    wmma::fragment<wmma::accumulator, 16, 16, 16, float> acc[2][4];
#pragma unroll
    for (int i = 0; i < 2; i++)
#pragma unroll
        for (int j = 0; j < 4; j++) wmma::fill_fragment(acc[i][j], 0.0f);

    const __nv_bfloat16* gsrc[4];
    gsrc[0] = g_Ahi + (size_t)bm * HDIM;
    gsrc[1] = g_Alo + (size_t)bm * HDIM;
    gsrc[2] = g_Bhi + (size_t)bn * HDIM;
    gsrc[3] = g_Blo + (size_t)bn * HDIM;

    const int lrow = tid >> 2;        // 0..63
    const int lc   = tid & 3;         // 16B vector index within 64B chunk
    auto load_chunk = [&](int k0, int buf) {
#pragma unroll
        for (int t = 0; t < 4; t++) {
            const __nv_bfloat16* src = gsrc[t] + k0;
            const uint32_t dstb = smbase + (uint32_t)(buf * BUF_ELEMS + t * TILE_ELEMS) * 2;
#pragma unroll
            for (int it = 0; it < 2; it++) {
                const int row = lrow + it * 64;
                const uint32_t d = dstb + (uint32_t)(row * LPAD + lc * 8) * 2;
                const void* s = src + (size_t)row * HDIM + lc * 8;
                asm volatile("cp.async.cg.shared.global [%0], [%1], 16;\n" :: "r"(d), "l"(s));
            }
        }
        asm volatile("cp.async.commit_group;\n" ::: "memory");
    };

    load_chunk(0, 0);
    int buf = 0;

    for (int c = 0; c < NCHUNK; c++) {
        asm volatile("cp.async.wait_group 0;\n" ::: "memory");
        __syncthreads();

        if (c + 1 < NCHUNK) load_chunk((c + 1) * KC, buf ^ 1);

        const __nv_bfloat16* sAhi = sm + buf * BUF_ELEMS;
        const __nv_bfloat16* sAlo = sAhi + TILE_ELEMS;
        const __nv_bfloat16* sBhi = sAhi + 2 * TILE_ELEMS;
        const __nv_bfloat16* sBlo = sAhi + 3 * TILE_ELEMS;

#pragma unroll
        for (int ks = 0; ks < KC; ks += 16) {
            wmma::fragment<wmma::matrix_a, 16, 16, 16, __nv_bfloat16, wmma::row_major> ah0, ah1, al0, al1;
            wmma::fragment<wmma::matrix_b, 16, 16, 16, __nv_bfloat16, wmma::col_major> b[4];

            wmma::load_matrix_sync(ah0, sAhi + (wm * 32 +  0) * LPAD + ks, LPAD);
            wmma::load_matrix_sync(ah1, sAhi + (wm * 32 + 16) * LPAD + ks, LPAD);
            wmma::load_matrix_sync(al0, sAlo + (wm * 32 +  0) * LPAD + ks, LPAD);
            wmma::load_matrix_sync(al1, sAlo + (wm * 32 + 16) * LPAD + ks, LPAD);

            // b_hi serves both hi*hi and lo*hi terms
#pragma unroll
            for (int ni = 0; ni < 4; ni++)
                wmma::load_matrix_sync(b[ni], sBhi + (wn * 64 + ni * 16) * LPAD + ks, LPAD);
#pragma unroll
            for (int ni = 0; ni < 4; ni++) {
                wmma::mma_sync(acc[0][ni], ah0, b[ni], acc[0][ni]);
                wmma::mma_sync(acc[1][ni], ah1, b[ni], acc[1][ni]);
                wmma::mma_sync(acc[0][ni], al0, b[ni], acc[0][ni]);
                wmma::mma_sync(acc[1][ni], al1, b[ni], acc[1][ni]);
            }
            // b_lo: hi*lo term
#pragma unroll
            for (int ni = 0; ni < 4; ni++)
                wmma::load_matrix_sync(b[ni], sBlo + (wn * 64 + ni * 16) * LPAD + ks, LPAD);
#pragma unroll
            for (int ni = 0; ni < 4; ni++) {
                wmma::mma_sync(acc[0][ni], ah0, b[ni], acc[0][ni]);
                wmma::mma_sync(acc[1][ni], ah1, b[ni], acc[1][ni]);
            }
        }
        buf ^= 1;
    }

    // Store: g_proj is padded to MPAD rows, no bounds checks needed.
#pragma unroll
    for (int mi = 0; mi < 2; mi++) {
        int row0 = bm + wm * 32 + mi * 16;
#pragma unroll
        for (int ni = 0; ni < 4; ni++) {
            float* cptr = g_proj + (size_t)row0 * PROJW + bn + wn * 64 + ni * 16;
            wmma::store_matrix_sync(cptr, acc[mi][ni], PROJW, wmma::mem_row_major);
        }
    }
}

// ---------------------------------------------------------------------------
// Edge phase v7: warp-per-node + edge-QUAD (KB=4) y-amortized scores.
// Chunk-wise inner loop keeps p/h transient; only acc[4][8] persists.
// Lane owns float4 chunks d4 = lane+32*i (i=0..3) of the 512-dim vectors.
// ---------------------------------------------------------------------------
#define WPB 8   // warps (=nodes) per block

__global__ __launch_bounds__(256) void edge_kernel(
    const float* __restrict__ z, const int* __restrict__ nbr,
    const int* __restrict__ bins, const float* __restrict__ y_w,
    const float* __restrict__ c_bins, const float* __restrict__ rw,
    float* __restrict__ out, int N)
{
    __shared__ float s_y[NHEADS * HDIM];          // 16 KB, block-shared
    __shared__ float s_sc[WPB][KNBR * NHEADS];    // 8 KB, per-warp scores/attn
    __shared__ float s_cb[NBINS * NHEADS];

    const int tid  = threadIdx.x;
    const int lane = tid & 31;
    const int warp = tid >> 5;

    for (int i = tid; i < NHEADS * HDIM; i += 256) s_y[i] = y_w[i];
    if (tid < NBINS * NHEADS) s_cb[tid] = c_bins[tid];
    __syncthreads();   // one-time init barrier

    const int node = blockIdx.x * WPB + warp;
    if (node >= N) return;

    const float rweight = rw[0];
    float* swsc = s_sc[warp];

    // lane's neighbor/bin (k = lane)
    const int m_l   = nbr[(size_t)node * KNBR + lane];
    const int bin_l = bins[(size_t)node * KNBR + lane];
    const unsigned validmask = __ballot_sync(0xffffffffu, m_l >= 0);

    if (validmask == 0u) {       // copy z verbatim
        const float4* zsrc = (const float4*)(z + (size_t)node * HDIM);
        float4* odst = (float4*)(out + (size_t)node * HDIM);
#pragma unroll
        for (int i = 0; i < 4; i++) odst[lane + 32 * i] = zsrc[lane + 32 * i];
        return;
    }

    // self projection: 4 float4 chunks, mapping d4 = lane+32*i
    float4 sreg[4];
    {
        const float4* srow = (const float4*)(g_proj + (size_t)node * PROJW);
#pragma unroll
        for (int i = 0; i < 4; i++) sreg[i] = srow[lane + 32 * i];
    }

    // ============ scores: 4 edges per pass, y loaded once per (chunk, head) ====
    for (int pass = 0; pass < KNBR / 4; pass++) {
        const int kb = pass * 4;
        int mk[4], bink[4];
        const float4* prow[4];
#pragma unroll
        for (int j = 0; j < 4; j++) {
            mk[j]   = __shfl_sync(0xffffffffu, m_l, kb + j);
            bink[j] = __shfl_sync(0xffffffffu, bin_l, kb + j);
            const int ms = mk[j] < 0 ? 0 : mk[j];
            prow[j] = (const float4*)(g_proj + (size_t)ms * PROJW + 512);
        }

        float acc[4][NHEADS];
#pragma unroll
        for (int j = 0; j < 4; j++)
#pragma unroll
            for (int e = 0; e < NHEADS; e++) acc[j][e] = 0.0f;

        const float4* yrow = (const float4*)s_y;
#pragma unroll
        for (int i = 0; i < 4; i++) {       // chunk; p/h transient
            float4 h[4];
#pragma unroll
            for (int j = 0; j < 4; j++) {
                const float4 p = prow[j][lane + 32 * i];
                h[j].x = lrelu(p.x + sreg[i].x);
                h[j].y = lrelu(p.y + sreg[i].y);
                h[j].z = lrelu(p.z + sreg[i].z);
                h[j].w = lrelu(p.w + sreg[i].w);
            }
#pragma unroll
            for (int e = 0; e < NHEADS; e++) {
                const float4 yv = yrow[e * 128 + lane + 32 * i];  // ONE load serves 4 edges
#pragma unroll
                for (int j = 0; j < 4; j++)
                    acc[j][e] += yv.x * h[j].x + yv.y * h[j].y
                               + yv.z * h[j].z + yv.w * h[j].w;
            }
        }

        // split-butterfly reduce, each of the 4 edges
#pragma unroll
        for (int j = 0; j < 4; j++) {
            float* a = acc[j];
            float t4[4];
            {
                const int b = (lane >> 4) & 1;
#pragma unroll
                for (int v = 0; v < 8; v++)
                    a[v] += __shfl_xor_sync(0xffffffffu, a[v], 16);
#pragma unroll
                for (int v = 0; v < 4; v++) t4[v] = a[b * 4 + v];
            }
            float t2a, t2b;
            {
                const int b = (lane >> 3) & 1;
#pragma unroll
                for (int v = 0; v < 4; v++)
                    t4[v] += __shfl_xor_sync(0xffffffffu, t4[v], 8);
                t2a = t4[b * 2 + 0];
                t2b = t4[b * 2 + 1];
            }
            float vfin;
            {
                const int b = (lane >> 2) & 1;
                t2a += __shfl_xor_sync(0xffffffffu, t2a, 4);
                t2b += __shfl_xor_sync(0xffffffffu, t2b, 4);
                vfin = b ? t2b : t2a;
            }
            vfin += __shfl_xor_sync(0xffffffffu, vfin, 2);
            vfin += __shfl_xor_sync(0xffffffffu, vfin, 1);

            if ((lane & 3) == 0) {
                const int e = ((lane & 16) >> 2) | ((lane & 8) >> 2) | ((lane & 4) >> 2);
                swsc[(kb + j) * NHEADS + e] =
                    (mk[j] >= 0) ? (vfin + s_cb[bink[j] * NHEADS + e]) : -1.0e9f;
            }
        }
    }
    __syncwarp();

    // ================= softmax (8 lanes, one head each) =================
    if (lane < NHEADS) {
        const int e = lane;
        float sc[KNBR];
        float mx = -3.0e38f;
#pragma unroll
        for (int k = 0; k < KNBR; k++) {
            sc[k] = swsc[k * NHEADS + e];
            mx = fmaxf(mx, sc[k]);
        }
        float sum = 0.0f;
#pragma unroll
        for (int k = 0; k < KNBR; k++) {
            sc[k] = expf(sc[k] - mx);
            sum += sc[k];
        }
        const float inv = 1.0f / sum;
#pragma unroll
        for (int k = 0; k < KNBR; k++)
            swsc[k * NHEADS + e] = sc[k] * inv;
    }
    __syncwarp();

    // ================= aggregate + residual =================
    // lane owns d4 chunks lane+32*i; head of chunk i: e = 2*i + (lane>=16)
    float4 agg[4];
#pragma unroll
    for (int i = 0; i < 4; i++) agg[i] = make_float4(0.f, 0.f, 0.f, 0.f);

    const int ebase = (lane >> 4);   // 0 or 1
    for (int k = 0; k < KNBR; k++) {
        const int m = __shfl_sync(0xffffffffu, m_l, k);
        if (m < 0) continue;         // warp-uniform; attn exactly 0
        const float4* wrow = (const float4*)(g_proj + (size_t)m * PROJW + 1024);
#pragma unroll
        for (int i = 0; i < 4; i++) {
            const float a = swsc[k * NHEADS + 2 * i + ebase];
            const float4 wv = wrow[lane + 32 * i];
            agg[i].x += a * wv.x;
            agg[i].y += a * wv.y;
            agg[i].z += a * wv.z;
            agg[i].w += a * wv.w;
        }
    }

    const float4* zsrc = (const float4*)(z + (size_t)node * HDIM);
    float4* odst = (float4*)(out + (size_t)node * HDIM);
#pragma unroll
    for (int i = 0; i < 4; i++) {
        const float4 zv = zsrc[lane + 32 * i];
        float4 ov;
        ov.x = lrelu(agg[i].x + rweight * zv.x);
        ov.y = lrelu(agg[i].y + rweight * zv.y);
        ov.z = lrelu(agg[i].z + rweight * zv.z);
        ov.w = lrelu(agg[i].w + rweight * zv.w);
        odst[lane + 32 * i] = ov;
    }
}

// ---------------------------------------------------------------------------
extern "C" void kernel_launch(void* const* d_in, const int* in_sizes, int n_in,
                              void* d_out, int out_size) {
    const float* z      = (const float*)d_in[0];
    // d_in[1] (A) is all zeros and unused by the reference — skipped.
    const int*   nbr    = (const int*)d_in[2];
    const int*   bins   = (const int*)d_in[3];
    const float* P_w    = (const float*)d_in[4];
    const float* y_w    = (const float*)d_in[5];
    const float* W_w    = (const float*)d_in[6];
    const float* c_bins = (const float*)d_in[7];
    const float* rw     = (const float*)d_in[8];
    float*       out    = (float*)d_out;

    const int N      = in_sizes[0] / HDIM;
    const int mtiles = (N + 127) / 128;
    const int Mp     = mtiles * 128;

    cudaFuncSetAttribute(gemm_wmma_kernel,
                         cudaFuncAttributeMaxDynamicSharedMemorySize, GEMM_SMEM);

    conv_a_kernel<<<(Mp * HDIM + 255) / 256, 256>>>(z, N, Mp);
    conv_b_kernel<<<(PROJW * HDIM + 255) / 256, 256>>>(P_w, W_w);

    dim3 g(PROJW / 128, mtiles);
    gemm_wmma_kernel<<<g, 256, GEMM_SMEM>>>(N);

    edge_kernel<<<(N + WPB - 1) / WPB, 256>>>(z, nbr, bins, y_w, c_bins, rw, out, N);
}

// round 15
// speedup vs baseline: 1.0891x; 1.0891x over previous
#include <cuda_runtime.h>
#include <cuda_bf16.h>
#include <mma.h>
#include <cstdint>

using namespace nvcuda;

#define HDIM  512
#define KNBR  32
#define NHEADS 8
#define NBINS 10
#define NMAX  10000
#define MPAD  10112      // ceil(10000/128)*128
#define NEG_SLOPE 0.2f
#define PROJW 1536       // [S | Pn | Wt]

__device__ float g_proj[(size_t)MPAD * PROJW];          // per-node projections (fp32)
__device__ __nv_bfloat16 g_Ahi[(size_t)MPAD * HDIM];
__device__ __nv_bfloat16 g_Alo[(size_t)MPAD * HDIM];
__device__ __nv_bfloat16 g_Bhi[(size_t)PROJW * HDIM];
__device__ __nv_bfloat16 g_Blo[(size_t)PROJW * HDIM];

__device__ __forceinline__ float lrelu(float x) {
    return x >= 0.0f ? x : NEG_SLOPE * x;
}

// ===========================================================================
// Conversions: fp32 -> (hi, lo) bf16 split
// ===========================================================================
__global__ void conv_a_kernel(const float* __restrict__ z, int M, int Mp) {
    int i = blockIdx.x * blockDim.x + threadIdx.x;
    if (i >= Mp * HDIM) return;
    int row = i >> 9;
    float x = (row < M) ? z[i] : 0.0f;
    __nv_bfloat16 h = __float2bfloat16(x);
    g_Ahi[i] = h;
    g_Alo[i] = __float2bfloat16(x - __bfloat162float(h));
}

__global__ void conv_b_kernel(const float* __restrict__ P_w, const float* __restrict__ W_w) {
    int i = blockIdx.x * blockDim.x + threadIdx.x;
    if (i >= PROJW * HDIM) return;
    int j = i >> 9;
    int hcol = i & (HDIM - 1);
    float x;
    if (j < 512)        x = P_w[(size_t)j * 1024 + hcol];
    else if (j < 1024)  x = P_w[(size_t)(j - 512) * 1024 + 512 + hcol];
    else                x = W_w[(size_t)(j - 1024) * 512 + hcol];
    __nv_bfloat16 h = __float2bfloat16(x);
    g_Bhi[i] = h;
    g_Blo[i] = __float2bfloat16(x - __bfloat162float(h));
}

// ===========================================================================
// wmma bf16 3-term GEMM with cp.async DOUBLE BUFFERING.
// CTA tile 128x128, 8 warps (4m x 2n), warp tile 32x64.
// K chunked by 32; 2 buffers x 4 tiles x 128x48 bf16 = 96 KB dynamic smem.
// ===========================================================================
#define KC 32
#define LPAD 48
#define TILE_ELEMS (128 * LPAD)
#define BUF_ELEMS  (4 * TILE_ELEMS)
#define GEMM_SMEM  (2 * BUF_ELEMS * 2)   // 98304 bytes
#define NCHUNK (HDIM / KC)               // 16

__global__ __launch_bounds__(256) void gemm_wmma_kernel(int M) {
    extern __shared__ __nv_bfloat16 sm[];
    const uint32_t smbase = (uint32_t)__cvta_generic_to_shared(sm);

    const int tid = threadIdx.x;
    const int wid = tid >> 5;
    const int bm = blockIdx.y * 128;
    const int bn = blockIdx.x * 128;
    const int wm = wid & 3;
    const int wn = wid >> 2;

    wmma::fragment<wmma::accumulator, 16, 16, 16, float> acc[2][4];
#pragma unroll
    for (int i = 0; i < 2; i++)
#pragma unroll
        for (int j = 0; j < 4; j++) wmma::fill_fragment(acc[i][j], 0.0f);

    const __nv_bfloat16* gsrc[4];
    gsrc[0] = g_Ahi + (size_t)bm * HDIM;
    gsrc[1] = g_Alo + (size_t)bm * HDIM;
    gsrc[2] = g_Bhi + (size_t)bn * HDIM;
    gsrc[3] = g_Blo + (size_t)bn * HDIM;

    const int lrow = tid >> 2;        // 0..63
    const int lc   = tid & 3;         // 16B vector index within 64B chunk
    auto load_chunk = [&](int k0, int buf) {
#pragma unroll
        for (int t = 0; t < 4; t++) {
            const __nv_bfloat16* src = gsrc[t] + k0;
            const uint32_t dstb = smbase + (uint32_t)(buf * BUF_ELEMS + t * TILE_ELEMS) * 2;
#pragma unroll
            for (int it = 0; it < 2; it++) {
                const int row = lrow + it * 64;
                const uint32_t d = dstb + (uint32_t)(row * LPAD + lc * 8) * 2;
                const void* s = src + (size_t)row * HDIM + lc * 8;
                asm volatile("cp.async.cg.shared.global [%0], [%1], 16;\n" :: "r"(d), "l"(s));
            }
        }
        asm volatile("cp.async.commit_group;\n" ::: "memory");
    };

    load_chunk(0, 0);
    int buf = 0;

    for (int c = 0; c < NCHUNK; c++) {
        asm volatile("cp.async.wait_group 0;\n" ::: "memory");
        __syncthreads();

        if (c + 1 < NCHUNK) load_chunk((c + 1) * KC, buf ^ 1);

        const __nv_bfloat16* sAhi = sm + buf * BUF_ELEMS;
        const __nv_bfloat16* sAlo = sAhi + TILE_ELEMS;
        const __nv_bfloat16* sBhi = sAhi + 2 * TILE_ELEMS;
        const __nv_bfloat16* sBlo = sAhi + 3 * TILE_ELEMS;

#pragma unroll
        for (int ks = 0; ks < KC; ks += 16) {
            wmma::fragment<wmma::matrix_a, 16, 16, 16, __nv_bfloat16, wmma::row_major> ah0, ah1, al0, al1;
            wmma::fragment<wmma::matrix_b, 16, 16, 16, __nv_bfloat16, wmma::col_major> b[4];

            wmma::load_matrix_sync(ah0, sAhi + (wm * 32 +  0) * LPAD + ks, LPAD);
            wmma::load_matrix_sync(ah1, sAhi + (wm * 32 + 16) * LPAD + ks, LPAD);
            wmma::load_matrix_sync(al0, sAlo + (wm * 32 +  0) * LPAD + ks, LPAD);
            wmma::load_matrix_sync(al1, sAlo + (wm * 32 + 16) * LPAD + ks, LPAD);

            // b_hi serves both hi*hi and lo*hi terms
#pragma unroll
            for (int ni = 0; ni < 4; ni++)
                wmma::load_matrix_sync(b[ni], sBhi + (wn * 64 + ni * 16) * LPAD + ks, LPAD);
#pragma unroll
            for (int ni = 0; ni < 4; ni++) {
                wmma::mma_sync(acc[0][ni], ah0, b[ni], acc[0][ni]);
                wmma::mma_sync(acc[1][ni], ah1, b[ni], acc[1][ni]);
                wmma::mma_sync(acc[0][ni], al0, b[ni], acc[0][ni]);
                wmma::mma_sync(acc[1][ni], al1, b[ni], acc[1][ni]);
            }
            // b_lo: hi*lo term
#pragma unroll
            for (int ni = 0; ni < 4; ni++)
                wmma::load_matrix_sync(b[ni], sBlo + (wn * 64 + ni * 16) * LPAD + ks, LPAD);
#pragma unroll
            for (int ni = 0; ni < 4; ni++) {
                wmma::mma_sync(acc[0][ni], ah0, b[ni], acc[0][ni]);
                wmma::mma_sync(acc[1][ni], ah1, b[ni], acc[1][ni]);
            }
        }
        buf ^= 1;
    }

    // Store: g_proj is padded to MPAD rows, no bounds checks needed.
#pragma unroll
    for (int mi = 0; mi < 2; mi++) {
        int row0 = bm + wm * 32 + mi * 16;
#pragma unroll
        for (int ni = 0; ni < 4; ni++) {
            float* cptr = g_proj + (size_t)row0 * PROJW + bn + wn * 64 + ni * 16;
            wmma::store_matrix_sync(cptr, acc[mi][ni], PROJW, wmma::mem_row_major);
        }
    }
}

// ---------------------------------------------------------------------------
// Edge phase v8: warp-per-node, KB=2 y-amortized scores with CHUNK-MAJOR
// inner loop (p/h transient -> low reg pressure) + 3 CTAs/SM pin.
// Lane owns float4 chunks d4 = lane+32*i (i=0..3) of the 512-dim vectors.
// ---------------------------------------------------------------------------
#define WPB 8   // warps (=nodes) per block

__global__ __launch_bounds__(256, 3) void edge_kernel(
    const float* __restrict__ z, const int* __restrict__ nbr,
    const int* __restrict__ bins, const float* __restrict__ y_w,
    const float* __restrict__ c_bins, const float* __restrict__ rw,
    float* __restrict__ out, int N)
{
    __shared__ float s_y[NHEADS * HDIM];          // 16 KB, block-shared
    __shared__ float s_sc[WPB][KNBR * NHEADS];    // 8 KB, per-warp scores/attn
    __shared__ float s_cb[NBINS * NHEADS];

    const int tid  = threadIdx.x;
    const int lane = tid & 31;
    const int warp = tid >> 5;

    for (int i = tid; i < NHEADS * HDIM; i += 256) s_y[i] = y_w[i];
    if (tid < NBINS * NHEADS) s_cb[tid] = c_bins[tid];
    __syncthreads();   // one-time init barrier

    const int node = blockIdx.x * WPB + warp;
    if (node >= N) return;

    const float rweight = rw[0];
    float* swsc = s_sc[warp];

    // lane's neighbor/bin (k = lane)
    const int m_l   = nbr[(size_t)node * KNBR + lane];
    const int bin_l = bins[(size_t)node * KNBR + lane];
    const unsigned validmask = __ballot_sync(0xffffffffu, m_l >= 0);

    if (validmask == 0u) {       // copy z verbatim
        const float4* zsrc = (const float4*)(z + (size_t)node * HDIM);
        float4* odst = (float4*)(out + (size_t)node * HDIM);
#pragma unroll
        for (int i = 0; i < 4; i++) odst[lane + 32 * i] = zsrc[lane + 32 * i];
        return;
    }

    // self projection: 4 float4 chunks, mapping d4 = lane+32*i
    float4 sreg[4];
    {
        const float4* srow = (const float4*)(g_proj + (size_t)node * PROJW);
#pragma unroll
        for (int i = 0; i < 4; i++) sreg[i] = srow[lane + 32 * i];
    }

    // ====== scores: 2 edges per pass, chunk-major (p/h transient) ======
    for (int pass = 0; pass < KNBR / 2; pass++) {
        const int k0 = pass * 2, k1 = pass * 2 + 1;
        const int m0   = __shfl_sync(0xffffffffu, m_l, k0);
        const int m1   = __shfl_sync(0xffffffffu, m_l, k1);
        const int bin0 = __shfl_sync(0xffffffffu, bin_l, k0);
        const int bin1 = __shfl_sync(0xffffffffu, bin_l, k1);
        const int ms0 = m0 < 0 ? 0 : m0;
        const int ms1 = m1 < 0 ? 0 : m1;

        const float4* prow0 = (const float4*)(g_proj + (size_t)ms0 * PROJW + 512);
        const float4* prow1 = (const float4*)(g_proj + (size_t)ms1 * PROJW + 512);

        float acc0[NHEADS], acc1[NHEADS];
#pragma unroll
        for (int e = 0; e < NHEADS; e++) { acc0[e] = 0.0f; acc1[e] = 0.0f; }

        const float4* yrow = (const float4*)s_y;
#pragma unroll
        for (int i = 0; i < 4; i++) {          // chunk-major: p/h live per-chunk only
            const float4 p0 = prow0[lane + 32 * i];
            const float4 p1 = prow1[lane + 32 * i];
            const float a0 = lrelu(p0.x + sreg[i].x);
            const float a1 = lrelu(p0.y + sreg[i].y);
            const float a2 = lrelu(p0.z + sreg[i].z);
            const float a3 = lrelu(p0.w + sreg[i].w);
            const float b0 = lrelu(p1.x + sreg[i].x);
            const float b1 = lrelu(p1.y + sreg[i].y);
            const float b2 = lrelu(p1.z + sreg[i].z);
            const float b3 = lrelu(p1.w + sreg[i].w);
#pragma unroll
            for (int e = 0; e < NHEADS; e++) {
                const float4 yv = yrow[e * 128 + lane + 32 * i];  // one load, 2 edges
                acc0[e] += yv.x * a0 + yv.y * a1 + yv.z * a2 + yv.w * a3;
                acc1[e] += yv.x * b0 + yv.y * b1 + yv.z * b2 + yv.w * b3;
            }
        }

        // split-butterfly reduce, both edges
#pragma unroll
        for (int which = 0; which < 2; which++) {
            float* acc = which ? acc1 : acc0;
            float t4[4];
            {
                const int b = (lane >> 4) & 1;
#pragma unroll
                for (int v = 0; v < 8; v++)
                    acc[v] += __shfl_xor_sync(0xffffffffu, acc[v], 16);
#pragma unroll
                for (int v = 0; v < 4; v++) t4[v] = acc[b * 4 + v];
            }
            float t2a, t2b;
            {
                const int b = (lane >> 3) & 1;
#pragma unroll
                for (int v = 0; v < 4; v++)
                    t4[v] += __shfl_xor_sync(0xffffffffu, t4[v], 8);
                t2a = t4[b * 2 + 0];
                t2b = t4[b * 2 + 1];
            }
            float vfin;
            {
                const int b = (lane >> 2) & 1;
                t2a += __shfl_xor_sync(0xffffffffu, t2a, 4);
                t2b += __shfl_xor_sync(0xffffffffu, t2b, 4);
                vfin = b ? t2b : t2a;
            }
            vfin += __shfl_xor_sync(0xffffffffu, vfin, 2);
            vfin += __shfl_xor_sync(0xffffffffu, vfin, 1);

            if ((lane & 3) == 0) {
                const int e = ((lane & 16) >> 2) | ((lane & 8) >> 2) | ((lane & 4) >> 2);
                const int m   = which ? m1 : m0;
                const int bin = which ? bin1 : bin0;
                const int k   = which ? k1 : k0;
                swsc[k * NHEADS + e] = (m >= 0) ? (vfin + s_cb[bin * NHEADS + e]) : -1.0e9f;
            }
        }
    }
    __syncwarp();

    // ================= softmax (8 lanes, one head each) =================
    if (lane < NHEADS) {
        const int e = lane;
        float sc[KNBR];
        float mx = -3.0e38f;
#pragma unroll
        for (int k = 0; k < KNBR; k++) {
            sc[k] = swsc[k * NHEADS + e];
            mx = fmaxf(mx, sc[k]);
        }
        float sum = 0.0f;
#pragma unroll
        for (int k = 0; k < KNBR; k++) {
            sc[k] = expf(sc[k] - mx);
            sum += sc[k];
        }
        const float inv = 1.0f / sum;
#pragma unroll
        for (int k = 0; k < KNBR; k++)
            swsc[k * NHEADS + e] = sc[k] * inv;
    }
    __syncwarp();

    // ================= aggregate + residual =================
    // lane owns d4 chunks lane+32*i; head of chunk i: e = 2*i + (lane>=16)
    float4 agg[4];
#pragma unroll
    for (int i = 0; i < 4; i++) agg[i] = make_float4(0.f, 0.f, 0.f, 0.f);

    const int ebase = (lane >> 4);   // 0 or 1
    for (int k = 0; k < KNBR; k++) {
        const int m = __shfl_sync(0xffffffffu, m_l, k);
        if (m < 0) continue;         // warp-uniform; attn exactly 0
        const float4* wrow = (const float4*)(g_proj + (size_t)m * PROJW + 1024);
#pragma unroll
        for (int i = 0; i < 4; i++) {
            const float a = swsc[k * NHEADS + 2 * i + ebase];
            const float4 wv = wrow[lane + 32 * i];
            agg[i].x += a * wv.x;
            agg[i].y += a * wv.y;
            agg[i].z += a * wv.z;
            agg[i].w += a * wv.w;
        }
    }

    const float4* zsrc = (const float4*)(z + (size_t)node * HDIM);
    float4* odst = (float4*)(out + (size_t)node * HDIM);
#pragma unroll
    for (int i = 0; i < 4; i++) {
        const float4 zv = zsrc[lane + 32 * i];
        float4 ov;
        ov.x = lrelu(agg[i].x + rweight * zv.x);
        ov.y = lrelu(agg[i].y + rweight * zv.y);
        ov.z = lrelu(agg[i].z + rweight * zv.z);
        ov.w = lrelu(agg[i].w + rweight * zv.w);
        odst[lane + 32 * i] = ov;
    }
}

// ---------------------------------------------------------------------------
extern "C" void kernel_launch(void* const* d_in, const int* in_sizes, int n_in,
                              void* d_out, int out_size) {
    const float* z      = (const float*)d_in[0];
    // d_in[1] (A) is all zeros and unused by the reference — skipped.
    const int*   nbr    = (const int*)d_in[2];
    const int*   bins   = (const int*)d_in[3];
    const float* P_w    = (const float*)d_in[4];
    const float* y_w    = (const float*)d_in[5];
    const float* W_w    = (const float*)d_in[6];
    const float* c_bins = (const float*)d_in[7];
    const float* rw     = (const float*)d_in[8];
    float*       out    = (float*)d_out;

    const int N      = in_sizes[0] / HDIM;
    const int mtiles = (N + 127) / 128;
    const int Mp     = mtiles * 128;

    cudaFuncSetAttribute(gemm_wmma_kernel,
                         cudaFuncAttributeMaxDynamicSharedMemorySize, GEMM_SMEM);

    conv_a_kernel<<<(Mp * HDIM + 255) / 256, 256>>>(z, N, Mp);
    conv_b_kernel<<<(PROJW * HDIM + 255) / 256, 256>>>(P_w, W_w);

    dim3 g(PROJW / 128, mtiles);
    gemm_wmma_kernel<<<g, 256, GEMM_SMEM>>>(N);

    edge_kernel<<<(N + WPB - 1) / WPB, 256>>>(z, nbr, bins, y_w, c_bins, rw, out, N);
}